// round 1
// baseline (speedup 1.0000x reference)
#include <cuda_runtime.h>
#include <math.h>

// Problem constants (fixed by the reference)
#define BB   4
#define W_   2000
#define I_   64
#define S_   64
#define T_   24
#define U_   32
#define US_  2
#define PER_ 2161
#define NND  8644          // BB * PER_
#define EMAX 147456        // >= N*16 + N = 146948

// ---------------- scratch (device globals; no allocation) ----------------
__device__ float g_X[NND * 300];               // 300-d text features per node
__device__ float g_HA[(size_t)NND * 1024];     // ping
__device__ float g_HB[(size_t)NND * 1024];     // pong
__device__ float g_F[(size_t)NND * 1024];      // per-layer f = h @ fc
__device__ float g_IMF[256 * 1024];            // image FC result before scatter
__device__ float g_EL[NND * 4];
__device__ float g_ER[NND * 4];
__device__ int   g_deg[NND + 1];
__device__ int   g_off[NND + 1];
__device__ int   g_cur[NND];
__device__ int   g_esrc[EMAX];                 // CSR (by dst) source lists

// ---------------- node feature kernels ----------------
__global__ void k_word(const int* __restrict__ aw, const float* __restrict__ we) {
    int i = blockIdx.x;                 // 0 .. B*W-1
    int b = i / W_, w = i - b * W_;
    const float* src = we + (size_t)aw[i] * 300;
    float* dst = g_X + (size_t)(b * PER_ + w) * 300;
    for (int d = threadIdx.x; d < 300; d += blockDim.x) dst[d] = src[d];
}

__global__ void k_zero_img() {
    int r = blockIdx.x;                 // 0 .. B*I-1
    int b = r / I_, i = r - b * I_;
    float* dst = g_X + (size_t)(b * PER_ + W_ + i) * 300;
    for (int d = threadIdx.x; d < 300; d += blockDim.x) dst[d] = 0.f;
}

__global__ void k_sent(const int* __restrict__ sent, const float* __restrict__ mask,
                       const float* __restrict__ we) {
    int i = blockIdx.x;                 // 0 .. B*S-1
    int b = i / S_, s = i - b * S_;
    const int*   sw = sent + (size_t)i * T_;
    const float* mk = mask + (size_t)i * T_;
    int d0 = threadIdx.x, d1 = d0 + 128, d2 = d0 + 256;
    float cnt = 0.f, a0 = 0.f, a1 = 0.f, a2 = 0.f;
    for (int t = 0; t < T_; t++) {
        float m = mk[t]; cnt += m;
        const float* row = we + (size_t)sw[t] * 300;
        a0 += m * row[d0];
        if (d1 < 300) a1 += m * row[d1];
        if (d2 < 300) a2 += m * row[d2];
    }
    float inv = 1.f / (cnt == 0.f ? 1.f : cnt);
    float* dst = g_X + (size_t)(b * PER_ + W_ + I_ + s) * 300;
    dst[d0] = a0 * inv;
    if (d1 < 300) dst[d1] = a1 * inv;
    if (d2 < 300) dst[d2] = a2 * inv;
}

__global__ void k_utt(const int* __restrict__ utt, const float* __restrict__ mask) {
    int i = blockIdx.x;                 // 0 .. B*U-1
    int b = i / U_, u = i - b * U_;
    const int*   ui = utt + (size_t)i * US_;
    const float* mk = mask + (size_t)i * US_;
    int d0 = threadIdx.x, d1 = d0 + 128, d2 = d0 + 256;
    float cnt = 0.f, a0 = 0.f, a1 = 0.f, a2 = 0.f;
    for (int t = 0; t < US_; t++) {
        float m = mk[t]; cnt += m;
        const float* row = g_X + (size_t)(b * PER_ + W_ + I_ + ui[t]) * 300;
        a0 += m * row[d0];
        if (d1 < 300) a1 += m * row[d1];
        if (d2 < 300) a2 += m * row[d2];
    }
    float inv = 1.f / (cnt == 0.f ? 1.f : cnt);
    float* dst = g_X + (size_t)(b * PER_ + W_ + I_ + S_ + u) * 300;
    dst[d0] = a0 * inv;
    if (d1 < 300) dst[d1] = a1 * inv;
    if (d2 < 300) dst[d2] = a2 * inv;
}

__global__ void k_sess() {
    int b = blockIdx.x;
    int d0 = threadIdx.x, d1 = d0 + 128, d2 = d0 + 256;
    float a0 = 0.f, a1 = 0.f, a2 = 0.f;
    for (int u = 0; u < U_; u++) {
        const float* row = g_X + (size_t)(b * PER_ + W_ + I_ + S_ + u) * 300;
        a0 += row[d0];
        if (d1 < 300) a1 += row[d1];
        if (d2 < 300) a2 += row[d2];
    }
    float inv = 1.f / (float)U_;
    float* dst = g_X + (size_t)(b * PER_ + W_ + I_ + S_ + U_) * 300;
    dst[d0] = a0 * inv;
    if (d1 < 300) dst[d1] = a1 * inv;
    if (d2 < 300) dst[d2] = a2 * inv;
}

// ---------------- SGEMM (128x128x8 tile, 8x8 per thread) ----------------
__device__ __forceinline__ const float* sel_in(int s, const float* ext) {
    if (s == 1) return g_X;
    if (s == 2) return g_HA;
    if (s == 3) return g_HB;
    return ext;
}
__device__ __forceinline__ float* sel_out(int s) {
    if (s == 1) return g_HA;
    if (s == 2) return g_HB;
    if (s == 3) return g_F;
    return g_IMF;
}

__global__ void sgemm(const float* __restrict__ Aext, int aSel,
                      const float* __restrict__ Bw,
                      const float* __restrict__ bias,
                      int cSel, int M, int Nc, int K) {
    const float* A = sel_in(aSel, Aext);
    float* C = sel_out(cSel);
    __shared__ float sA[8][128];
    __shared__ float sB[8][128];
    int tid = threadIdx.x;              // 256 threads
    int tx = tid & 15, ty = tid >> 4;
    int row0 = blockIdx.y * 128, col0 = blockIdx.x * 128;
    float acc[8][8];
#pragma unroll
    for (int i = 0; i < 8; i++)
#pragma unroll
        for (int j = 0; j < 8; j++) acc[i][j] = 0.f;
    int aRow = tid >> 1, aCol = (tid & 1) * 4;
    int bRow = tid >> 5, bCol = (tid & 31) * 4;
    int arow_g = row0 + aRow;
    for (int k0 = 0; k0 < K; k0 += 8) {
#pragma unroll
        for (int i = 0; i < 4; i++) {
            int c = k0 + aCol + i;
            sA[aCol + i][aRow] = (arow_g < M && c < K) ? A[(size_t)arow_g * K + c] : 0.f;
        }
        int r = k0 + bRow;
#pragma unroll
        for (int i = 0; i < 4; i++) {
            sB[bRow][bCol + i] = (r < K) ? Bw[(size_t)r * Nc + col0 + bCol + i] : 0.f;
        }
        __syncthreads();
#pragma unroll
        for (int kk = 0; kk < 8; kk++) {
            float ra[8], rb[8];
#pragma unroll
            for (int i = 0; i < 8; i++) ra[i] = sA[kk][ty * 8 + i];
#pragma unroll
            for (int j = 0; j < 8; j++) rb[j] = sB[kk][tx * 8 + j];
#pragma unroll
            for (int i = 0; i < 8; i++)
#pragma unroll
                for (int j = 0; j < 8; j++) acc[i][j] += ra[i] * rb[j];
        }
        __syncthreads();
    }
#pragma unroll
    for (int i = 0; i < 8; i++) {
        int rr = row0 + ty * 8 + i;
        if (rr >= M) continue;
#pragma unroll
        for (int j = 0; j < 8; j++) {
            int c = col0 + tx * 8 + j;
            float v = acc[i][j];
            if (bias) v += bias[c];
            C[(size_t)rr * Nc + c] = v;
        }
    }
}

__global__ void k_scatter_imf() {
    int r = blockIdx.x;                 // 0 .. 255
    int b = r / I_, i = r - b * I_;
    const float* src = g_IMF + (size_t)r * 1024;
    float* dst = g_HA + (size_t)(b * PER_ + W_ + i) * 1024;
    for (int d = threadIdx.x; d < 1024; d += blockDim.x) dst[d] = src[d];
}

// ---------------- CSR by dst ----------------
__global__ void k_zero_deg() {
    int i = blockIdx.x * blockDim.x + threadIdx.x;
    if (i <= NND) g_deg[i] = 0;
}
__global__ void k_count(const int* __restrict__ dst, int E) {
    int e = blockIdx.x * blockDim.x + threadIdx.x;
    if (e < E) atomicAdd(&g_deg[dst[e]], 1);
}
__global__ void k_scan() {
    __shared__ int sh[1024];
    int tid = threadIdx.x;
    const int chunk = (NND + 1023) >> 10;
    int lo = tid * chunk;
    int hi = lo + chunk; if (hi > NND) hi = NND; if (lo > NND) lo = NND;
    int sum = 0;
    for (int i = lo; i < hi; i++) sum += g_deg[i];
    sh[tid] = sum; __syncthreads();
    for (int d = 1; d < 1024; d <<= 1) {
        int v = 0;
        if (tid >= d) v = sh[tid - d];
        __syncthreads();
        if (tid >= d) sh[tid] += v;
        __syncthreads();
    }
    int run = (tid == 0) ? 0 : sh[tid - 1];
    for (int i = lo; i < hi; i++) {
        g_off[i] = run; g_cur[i] = run; run += g_deg[i];
    }
    if (tid == 1023) g_off[NND] = run;
}
__global__ void k_fill(const int* __restrict__ src, const int* __restrict__ dst, int E) {
    int e = blockIdx.x * blockDim.x + threadIdx.x;
    if (e < E) {
        int p = atomicAdd(&g_cur[dst[e]], 1);
        g_esrc[p] = src[e];
    }
}

// ---------------- GAT attention pieces ----------------
template <int NH, int DD>
__global__ void k_elr(const float* __restrict__ al, const float* __restrict__ ar) {
    int gw = (blockIdx.x * blockDim.x + threadIdx.x) >> 5;
    int lane = threadIdx.x & 31;
    if (gw >= NND) return;
    const float* f = g_F + (size_t)gw * (NH * DD);
#pragma unroll
    for (int h = 0; h < NH; h++) {
        float sl = 0.f, sr = 0.f;
        for (int d = lane; d < DD; d += 32) {
            float v = f[h * DD + d];
            sl += v * al[h * DD + d];
            sr += v * ar[h * DD + d];
        }
#pragma unroll
        for (int o = 16; o; o >>= 1) {
            sl += __shfl_xor_sync(0xffffffffu, sl, o);
            sr += __shfl_xor_sync(0xffffffffu, sr, o);
        }
        if (lane == 0) { g_EL[gw * NH + h] = sl; g_ER[gw * NH + h] = sr; }
    }
}

// One 128-thread block per dst node. Two-pass stable softmax over incoming
// edges, then chunked aggregation of alpha * f[src].
template <int NH, int DD, bool ACT>
__global__ void k_attn(const float* __restrict__ bias, int outSel) {
    constexpr int WID = NH * DD;
    constexpr int NE  = WID / 128;
    constexpr int CE  = 128 / NH;
    float* Hout = (outSel == 1) ? g_HA : g_HB;

    int nd  = blockIdx.x;
    int tid = threadIdx.x;
    int lo  = g_off[nd];
    int deg = g_off[nd + 1] - lo;

    __shared__ float s_er[NH], s_m[NH], s_iz[NH];
    __shared__ float red[128];
    __shared__ float swt[32 * NH];
    __shared__ int   ssrc[32];

    if (tid < NH) s_er[tid] = g_ER[nd * NH + tid];
    __syncthreads();

    int h  = tid / CE;
    int e0 = tid % CE;
    float erh = s_er[h];

    // pass 1: max
    float lmax = -1e30f;
    for (int e = e0; e < deg; e += CE) {
        int s = g_esrc[lo + e];
        float x = g_EL[s * NH + h] + erh;
        x = x > 0.f ? x : 0.2f * x;
        lmax = fmaxf(lmax, x);
    }
    red[tid] = lmax; __syncthreads();
#pragma unroll
    for (int st = CE / 2; st > 0; st >>= 1) {
        if (e0 < st) red[tid] = fmaxf(red[tid], red[tid + st]);
        __syncthreads();
    }
    if (e0 == 0) s_m[h] = red[tid];
    __syncthreads();
    float mh = s_m[h];

    // pass 2: sum of exp
    float lsum = 0.f;
    for (int e = e0; e < deg; e += CE) {
        int s = g_esrc[lo + e];
        float x = g_EL[s * NH + h] + erh;
        x = x > 0.f ? x : 0.2f * x;
        lsum += expf(x - mh);
    }
    red[tid] = lsum; __syncthreads();
#pragma unroll
    for (int st = CE / 2; st > 0; st >>= 1) {
        if (e0 < st) red[tid] += red[tid + st];
        __syncthreads();
    }
    if (e0 == 0) s_iz[h] = 1.f / red[tid];
    __syncthreads();

    // pass 3: aggregate alpha * f[src]
    float accv[NE];
    int hd[NE];
#pragma unroll
    for (int j = 0; j < NE; j++) { accv[j] = 0.f; hd[j] = (tid + j * 128) / DD; }

    for (int base = 0; base < deg; base += 32) {
        int mcnt = deg - base; if (mcnt > 32) mcnt = 32;
        if (tid < 32 * NH) {
            int eL = tid / NH, hh = tid - (tid / NH) * NH;
            float wv = 0.f;
            if (eL < mcnt) {
                int s = g_esrc[lo + base + eL];
                float x = g_EL[s * NH + hh] + s_er[hh];
                x = x > 0.f ? x : 0.2f * x;
                wv = expf(x - s_m[hh]) * s_iz[hh];
                if (hh == 0) ssrc[eL] = s;
            }
            swt[eL * NH + hh] = wv;
        }
        __syncthreads();
        for (int eL = 0; eL < mcnt; eL++) {
            int s = ssrc[eL];
            const float* fr = g_F + (size_t)s * WID;
#pragma unroll
            for (int j = 0; j < NE; j++)
                accv[j] += swt[eL * NH + hd[j]] * fr[tid + j * 128];
        }
        __syncthreads();
    }

#pragma unroll
    for (int j = 0; j < NE; j++) {
        int c = tid + j * 128;
        float v = accv[j] + bias[c];
        if (ACT) v = v > 0.f ? v : (expf(v) - 1.f);
        Hout[(size_t)nd * WID + c] = v;
    }
}

__global__ void k_out(const int* __restrict__ sid, float* __restrict__ out) {
    int b = blockIdx.x;
    out[(size_t)b * 512 + threadIdx.x] = g_HB[(size_t)sid[b] * 512 + threadIdx.x];
}

// ---------------- launch ----------------
extern "C" void kernel_launch(void* const* d_in, const int* in_sizes, int n_in,
                              void* d_out, int out_size) {
    const int*   all_words      = (const int*)  d_in[0];
    const float* image_feats    = (const float*)d_in[1];
    const int*   sentences      = (const int*)  d_in[2];
    const float* sentence_mask  = (const float*)d_in[3];
    const int*   utterances     = (const int*)  d_in[4];
    const float* utterance_mask = (const float*)d_in[5];
    const int*   session_ids    = (const int*)  d_in[6];
    const int*   edge_src       = (const int*)  d_in[7];
    const int*   edge_dst       = (const int*)  d_in[8];
    const float* word_embed     = (const float*)d_in[9];
    const float* text_fc_w      = (const float*)d_in[10];
    const float* text_fc_b      = (const float*)d_in[11];
    const float* image_fc_w     = (const float*)d_in[12];
    const float* image_fc_b     = (const float*)d_in[13];
    const float* gat0_fc = (const float*)d_in[14];
    const float* gat0_al = (const float*)d_in[15];
    const float* gat0_ar = (const float*)d_in[16];
    const float* gat0_b  = (const float*)d_in[17];
    const float* gat1_fc = (const float*)d_in[18];
    const float* gat1_al = (const float*)d_in[19];
    const float* gat1_ar = (const float*)d_in[20];
    const float* gat1_b  = (const float*)d_in[21];
    const float* gat2_fc = (const float*)d_in[22];
    const float* gat2_al = (const float*)d_in[23];
    const float* gat2_ar = (const float*)d_in[24];
    const float* gat2_b  = (const float*)d_in[25];
    float* out = (float*)d_out;
    int E = in_sizes[7];

    // node features (300-d text space)
    k_word<<<BB * W_, 128>>>(all_words, word_embed);
    k_zero_img<<<BB * I_, 128>>>();
    k_sent<<<BB * S_, 128>>>(sentences, sentence_mask, word_embed);
    k_utt<<<BB * U_, 128>>>(utterances, utterance_mask);
    k_sess<<<BB, 128>>>();

    dim3 blk(256);
    dim3 gText(1024 / 128, (NND + 127) / 128);
    sgemm<<<gText, blk>>>(nullptr, 1, text_fc_w, text_fc_b, 1, NND, 1024, 300);   // X -> HA
    dim3 gImg(1024 / 128, (256 + 127) / 128);
    sgemm<<<gImg, blk>>>(image_feats, 0, image_fc_w, image_fc_b, 4, 256, 1024, 2048); // -> IMF
    k_scatter_imf<<<BB * I_, 128>>>();

    // CSR by dst (edges identical across layers)
    k_zero_deg<<<(NND + 1 + 255) / 256, 256>>>();
    k_count<<<(E + 255) / 256, 256>>>(edge_dst, E);
    k_scan<<<1, 1024>>>();
    k_fill<<<(E + 255) / 256, 256>>>(edge_src, edge_dst, E);

    dim3 gFull(1024 / 128, (NND + 127) / 128);
    int elrBlocks = (NND + 3) / 4;

    // layer 0: HA -> F -> HB
    sgemm<<<gFull, blk>>>(nullptr, 2, gat0_fc, nullptr, 3, NND, 1024, 1024);
    k_elr<4, 256><<<elrBlocks, 128>>>(gat0_al, gat0_ar);
    k_attn<4, 256, true><<<NND, 128>>>(gat0_b, 2);

    // layer 1: HB -> F -> HA
    sgemm<<<gFull, blk>>>(nullptr, 3, gat1_fc, nullptr, 3, NND, 1024, 1024);
    k_elr<4, 256><<<elrBlocks, 128>>>(gat1_al, gat1_ar);
    k_attn<4, 256, true><<<NND, 128>>>(gat1_b, 1);

    // layer 2: HA -> F(512) -> HB(512)
    dim3 gL2(512 / 128, (NND + 127) / 128);
    sgemm<<<gL2, blk>>>(nullptr, 2, gat2_fc, nullptr, 3, NND, 512, 1024);
    k_elr<1, 512><<<elrBlocks, 128>>>(gat2_al, gat2_ar);
    k_attn<1, 512, false><<<NND, 128>>>(gat2_b, 2);

    k_out<<<BB, 512>>>(session_ids, out);
}

// round 2
// speedup vs baseline: 2.4007x; 2.4007x over previous
#include <cuda_runtime.h>
#include <math.h>

// Problem constants (fixed by the reference)
#define BB   4
#define W_   2000
#define I_   64
#define S_   64
#define T_   24
#define U_   32
#define US_  2
#define PER_ 2161
#define NND  8644
#define EMAX 147456
#define KS   4            // split-K factor for small GEMM

// ---------------- scratch (device globals; no allocation) ----------------
__device__ float g_X[NND * 300];
__device__ float g_HA[(size_t)NND * 1024];
__device__ float g_HB[(size_t)NND * 1024];
__device__ float g_F[(size_t)NND * 1024];
__device__ float g_IMF[256 * 1024];
__device__ float g_P[(size_t)KS * NND * 1024];   // split-K partials
__device__ float g_EL[NND * 4];
__device__ float g_ER[NND * 4];
__device__ int   g_deg[NND + 1];
__device__ int   g_off[NND + 1];
__device__ int   g_cur[NND];
__device__ int   g_esrc[EMAX];
__device__ unsigned char g_S[NND], g_A1f[NND], g_R1f[NND];
__device__ int   g_list1[NND], g_listR[NND];
__device__ int   g_cnt1, g_cntR;
__device__ int   g_four = 4;

// ---------------- f32x2 helpers ----------------
typedef unsigned long long ull;
__device__ __forceinline__ ull pk2(float a, float b) {
    ull r; asm("mov.b64 %0,{%1,%2};" : "=l"(r) : "f"(a), "f"(b)); return r;
}
__device__ __forceinline__ void upk2(ull v, float& a, float& b) {
    asm("mov.b64 {%0,%1},%2;" : "=f"(a), "=f"(b) : "l"(v));
}
__device__ __forceinline__ void fma2(ull& d, ull a, ull b) {
    asm("fma.rn.f32x2 %0,%1,%2,%0;" : "+l"(d) : "l"(a), "l"(b));
}

// ---------------- selectors (device-global buffers by id) ----------------
__device__ __forceinline__ const float* sel_in(int s, const float* ext) {
    if (s == 1) return g_X;
    if (s == 2) return g_HA;
    if (s == 3) return g_HB;
    return ext;
}
__device__ __forceinline__ float* sel_out(int s) {
    if (s == 1) return g_HA;
    if (s == 2) return g_HB;
    if (s == 3) return g_F;
    return g_IMF;
}
__device__ __forceinline__ const int* sel_list(int s, const int* ext) {
    if (s == 1) return g_list1;
    if (s == 2) return g_listR;
    if (s == 3) return ext;
    return nullptr;
}
__device__ __forceinline__ const int* sel_cnt(int s) {
    if (s == 1) return &g_cnt1;
    if (s == 2) return &g_cntR;
    if (s == 3) return &g_four;
    return nullptr;
}

// ---------------- node feature kernels ----------------
__global__ void k_word(const int* __restrict__ aw, const float* __restrict__ we) {
    int i = blockIdx.x;
    int b = i / W_, w = i - b * W_;
    const float* src = we + (size_t)aw[i] * 300;
    float* dst = g_X + (size_t)(b * PER_ + w) * 300;
    for (int d = threadIdx.x; d < 300; d += blockDim.x) dst[d] = src[d];
}

__global__ void k_zero_img() {
    int r = blockIdx.x;
    int b = r / I_, i = r - b * I_;
    float* dst = g_X + (size_t)(b * PER_ + W_ + i) * 300;
    for (int d = threadIdx.x; d < 300; d += blockDim.x) dst[d] = 0.f;
}

__global__ void k_sent(const int* __restrict__ sent, const float* __restrict__ mask,
                       const float* __restrict__ we) {
    int i = blockIdx.x;
    int b = i / S_, s = i - b * S_;
    const int*   sw = sent + (size_t)i * T_;
    const float* mk = mask + (size_t)i * T_;
    int d0 = threadIdx.x, d1 = d0 + 128, d2 = d0 + 256;
    float cnt = 0.f, a0 = 0.f, a1 = 0.f, a2 = 0.f;
    for (int t = 0; t < T_; t++) {
        float m = mk[t]; cnt += m;
        const float* row = we + (size_t)sw[t] * 300;
        a0 += m * row[d0];
        if (d1 < 300) a1 += m * row[d1];
        if (d2 < 300) a2 += m * row[d2];
    }
    float inv = 1.f / (cnt == 0.f ? 1.f : cnt);
    float* dst = g_X + (size_t)(b * PER_ + W_ + I_ + s) * 300;
    dst[d0] = a0 * inv;
    if (d1 < 300) dst[d1] = a1 * inv;
    if (d2 < 300) dst[d2] = a2 * inv;
}

__global__ void k_utt(const int* __restrict__ utt, const float* __restrict__ mask) {
    int i = blockIdx.x;
    int b = i / U_, u = i - b * U_;
    const int*   ui = utt + (size_t)i * US_;
    const float* mk = mask + (size_t)i * US_;
    int d0 = threadIdx.x, d1 = d0 + 128, d2 = d0 + 256;
    float cnt = 0.f, a0 = 0.f, a1 = 0.f, a2 = 0.f;
    for (int t = 0; t < US_; t++) {
        float m = mk[t]; cnt += m;
        const float* row = g_X + (size_t)(b * PER_ + W_ + I_ + ui[t]) * 300;
        a0 += m * row[d0];
        if (d1 < 300) a1 += m * row[d1];
        if (d2 < 300) a2 += m * row[d2];
    }
    float inv = 1.f / (cnt == 0.f ? 1.f : cnt);
    float* dst = g_X + (size_t)(b * PER_ + W_ + I_ + S_ + u) * 300;
    dst[d0] = a0 * inv;
    if (d1 < 300) dst[d1] = a1 * inv;
    if (d2 < 300) dst[d2] = a2 * inv;
}

__global__ void k_sess() {
    int b = blockIdx.x;
    int d0 = threadIdx.x, d1 = d0 + 128, d2 = d0 + 256;
    float a0 = 0.f, a1 = 0.f, a2 = 0.f;
    for (int u = 0; u < U_; u++) {
        const float* row = g_X + (size_t)(b * PER_ + W_ + I_ + S_ + u) * 300;
        a0 += row[d0];
        if (d1 < 300) a1 += row[d1];
        if (d2 < 300) a2 += row[d2];
    }
    float inv = 1.f / (float)U_;
    float* dst = g_X + (size_t)(b * PER_ + W_ + I_ + S_ + U_) * 300;
    dst[d0] = a0 * inv;
    if (d1 < 300) dst[d1] = a1 * inv;
    if (d2 < 300) dst[d2] = a2 * inv;
}

// ---------------- big f32x2 GEMM: 128(M) x 256(N) block, 8x16 per thread ----
__global__ __launch_bounds__(256, 1)
void gemm_big(const float* __restrict__ Aext, int aSel,
              const float* __restrict__ Bw,
              const float* __restrict__ bias,
              int cSel, int M, int Nc, int K) {
    const float* A = sel_in(aSel, Aext);
    float* C = sel_out(cSel);
    __shared__ float sA[8][128];
    __shared__ float sB[8][256];
    int tid = threadIdx.x;
    int tx = tid & 15, ty = tid >> 4;
    int row0 = blockIdx.y * 128, col0 = blockIdx.x * 256;

    ull acc[8][8];
#pragma unroll
    for (int i = 0; i < 8; i++)
#pragma unroll
        for (int j = 0; j < 8; j++) acc[i][j] = 0ull;

    int aRow = tid >> 1, aCol = (tid & 1) * 4;
    int bRow = tid >> 5, bCol = (tid & 31) * 8;
    int rg = row0 + aRow;
    bool av = rg < M;
    const float* Arow = A + (size_t)(av ? rg : 0) * K;

    for (int k0 = 0; k0 < K; k0 += 8) {
        // A fill
        if (av && k0 + 8 <= K) {
            float4 v = *(const float4*)(Arow + k0 + aCol);
            sA[aCol + 0][aRow] = v.x;
            sA[aCol + 1][aRow] = v.y;
            sA[aCol + 2][aRow] = v.z;
            sA[aCol + 3][aRow] = v.w;
        } else {
#pragma unroll
            for (int i = 0; i < 4; i++) {
                int c = k0 + aCol + i;
                sA[aCol + i][aRow] = (av && c < K) ? Arow[c] : 0.f;
            }
        }
        // B fill
        int r = k0 + bRow;
        if (r < K) {
            const float* Br = Bw + (size_t)r * Nc + col0 + bCol;
            float4 v0 = *(const float4*)Br;
            float4 v1 = *(const float4*)(Br + 4);
            sB[bRow][bCol + 0] = v0.x; sB[bRow][bCol + 1] = v0.y;
            sB[bRow][bCol + 2] = v0.z; sB[bRow][bCol + 3] = v0.w;
            sB[bRow][bCol + 4] = v1.x; sB[bRow][bCol + 5] = v1.y;
            sB[bRow][bCol + 6] = v1.z; sB[bRow][bCol + 7] = v1.w;
        } else {
#pragma unroll
            for (int i = 0; i < 8; i++) sB[bRow][bCol + i] = 0.f;
        }
        __syncthreads();
#pragma unroll
        for (int kk = 0; kk < 8; kk++) {
            ull bp[8];
#pragma unroll
            for (int j = 0; j < 8; j++)
                bp[j] = *(const ull*)&sB[kk][32 * j + 2 * tx];
#pragma unroll
            for (int i = 0; i < 8; i++) {
                float a = sA[kk][ty * 8 + i];
                ull ap = pk2(a, a);
#pragma unroll
                for (int j = 0; j < 8; j++) fma2(acc[i][j], ap, bp[j]);
            }
        }
        __syncthreads();
    }
#pragma unroll
    for (int i = 0; i < 8; i++) {
        int rr = row0 + ty * 8 + i;
        if (rr >= M) continue;
#pragma unroll
        for (int j = 0; j < 8; j++) {
            int c = col0 + 32 * j + 2 * tx;
            float c0, c1; upk2(acc[i][j], c0, c1);
            if (bias) { c0 += bias[c]; c1 += bias[c + 1]; }
            float2 o; o.x = c0; o.y = c1;
            *(float2*)&C[(size_t)rr * Nc + c] = o;
        }
    }
}

// ---------------- small gathered split-K GEMM: 64x128 block, 4x8/thread ----
__global__ __launch_bounds__(256)
void gemm_sk(const float* __restrict__ Aext, int aSel,
             const float* __restrict__ Bw,
             int M, int Nc, int K, int rowSel, int cntSel,
             const int* __restrict__ extList) {
    const int* cntPtr = sel_cnt(cntSel);
    int cnt = cntPtr ? *cntPtr : M;
    const int* rows = sel_list(rowSel, extList);
    const float* A = sel_in(aSel, Aext);
    __shared__ float sA[8][64];
    __shared__ float sB[8][128];
    int tid = threadIdx.x;
    int tx = tid & 15, ty = tid >> 4;
    int col0 = blockIdx.x * 128;
    int z = blockIdx.z;
    int Kc = (((K + KS - 1) / KS) + 7) & ~7;
    int kbeg = z * Kc, kend = K < kbeg + Kc ? K : kbeg + Kc;

    int aRow = tid >> 2, aColB = (tid & 3) * 2;
    int bRow = tid >> 5, bCol = (tid & 31) * 4;

    for (int ry = blockIdx.y; ry * 64 < cnt; ry += gridDim.y) {
        int row0 = ry * 64;
        int rg = row0 + aRow;
        bool av = rg < cnt;
        int grow = av ? (rows ? rows[rg] : rg) : 0;
        const float* Arow = A + (size_t)grow * K;

        ull acc[2][8];
#pragma unroll
        for (int i = 0; i < 2; i++)
#pragma unroll
            for (int j = 0; j < 8; j++) acc[i][j] = 0ull;

        for (int k0 = kbeg; k0 < kend; k0 += 8) {
#pragma unroll
            for (int i = 0; i < 2; i++) {
                int c = k0 + aColB + i;
                sA[aColB + i][aRow] = (av && c < kend) ? Arow[c] : 0.f;
            }
            int r = k0 + bRow;
            if (r < kend) {
                float4 v = *(const float4*)(Bw + (size_t)r * Nc + col0 + bCol);
                sB[bRow][bCol + 0] = v.x; sB[bRow][bCol + 1] = v.y;
                sB[bRow][bCol + 2] = v.z; sB[bRow][bCol + 3] = v.w;
            } else {
#pragma unroll
                for (int i = 0; i < 4; i++) sB[bRow][bCol + i] = 0.f;
            }
            __syncthreads();
#pragma unroll
            for (int kk = 0; kk < 8; kk++) {
                ull ap0 = *(const ull*)&sA[kk][ty * 4];
                ull ap1 = *(const ull*)&sA[kk][ty * 4 + 2];
#pragma unroll
                for (int j = 0; j < 8; j++) {
                    float b = sB[kk][tx + 16 * j];
                    ull bb = pk2(b, b);
                    fma2(acc[0][j], ap0, bb);
                    fma2(acc[1][j], ap1, bb);
                }
            }
            __syncthreads();
        }
        float* P = g_P + (size_t)z * NND * 1024;
#pragma unroll
        for (int ii = 0; ii < 2; ii++) {
            int r0 = row0 + ty * 4 + 2 * ii;
#pragma unroll
            for (int j = 0; j < 8; j++) {
                float c0, c1; upk2(acc[ii][j], c0, c1);
                int col = col0 + tx + 16 * j;
                if (r0 < cnt)     P[(size_t)r0 * Nc + col] = c0;
                if (r0 + 1 < cnt) P[(size_t)(r0 + 1) * Nc + col] = c1;
            }
        }
    }
}

__global__ void k_reduce(const float* __restrict__ bias, int cSel, int Nc,
                         int rowSel, int cntSel, int M,
                         const int* __restrict__ extList) {
    const int* cntPtr = sel_cnt(cntSel);
    int cnt = cntPtr ? *cntPtr : M;
    const int* rows = sel_list(rowSel, extList);
    float* C = sel_out(cSel);
    long total = (long)cnt * Nc;
    long stride = (long)gridDim.x * blockDim.x;
    for (long i = (long)blockIdx.x * blockDim.x + threadIdx.x; i < total; i += stride) {
        int r = (int)(i / Nc);
        int col = (int)(i - (long)r * Nc);
        float s = bias ? bias[col] : 0.f;
#pragma unroll
        for (int z = 0; z < KS; z++)
            s += g_P[(size_t)z * NND * 1024 + (size_t)i];
        int orow = rows ? rows[r] : r;
        C[(size_t)orow * Nc + col] = s;
    }
}

__global__ void k_scatter_imf() {
    int r = blockIdx.x;
    int b = r / I_, i = r - b * I_;
    const float* src = g_IMF + (size_t)r * 1024;
    float* dst = g_HA + (size_t)(b * PER_ + W_ + i) * 1024;
    for (int d = threadIdx.x; d < 1024; d += blockDim.x) dst[d] = src[d];
}

// ---------------- active-set computation ----------------
__global__ void k_zero_sets() {
    int i = blockIdx.x * blockDim.x + threadIdx.x;
    if (i < NND) { g_S[i] = 0; g_A1f[i] = 0; g_R1f[i] = 0; }
    if (i == 0) { g_cnt1 = 0; g_cntR = 0; }
}
__global__ void k_markS(const int* __restrict__ sid) {
    g_S[sid[threadIdx.x]] = 1;
}
__global__ void k_markA1(const int* __restrict__ src, const int* __restrict__ dst, int E) {
    int e = blockIdx.x * blockDim.x + threadIdx.x;
    if (e < E && g_S[dst[e]]) g_A1f[src[e]] = 1;
}
__global__ void k_markR1(const int* __restrict__ src, const int* __restrict__ dst, int E) {
    int e = blockIdx.x * blockDim.x + threadIdx.x;
    if (e < E && g_A1f[dst[e]]) g_R1f[src[e]] = 1;
}
__global__ void k_compact() {
    int i = blockIdx.x * blockDim.x + threadIdx.x;
    if (i < NND) {
        if (g_A1f[i]) g_list1[atomicAdd(&g_cnt1, 1)] = i;
        if (g_R1f[i]) g_listR[atomicAdd(&g_cntR, 1)] = i;
    }
}

// ---------------- CSR by dst ----------------
__global__ void k_zero_deg() {
    int i = blockIdx.x * blockDim.x + threadIdx.x;
    if (i <= NND) g_deg[i] = 0;
}
__global__ void k_count(const int* __restrict__ dst, int E) {
    int e = blockIdx.x * blockDim.x + threadIdx.x;
    if (e < E) atomicAdd(&g_deg[dst[e]], 1);
}
__global__ void k_scan() {
    __shared__ int sh[1024];
    int tid = threadIdx.x;
    const int chunk = (NND + 1023) >> 10;
    int lo = tid * chunk;
    int hi = lo + chunk; if (hi > NND) hi = NND; if (lo > NND) lo = NND;
    int sum = 0;
    for (int i = lo; i < hi; i++) sum += g_deg[i];
    sh[tid] = sum; __syncthreads();
    for (int d = 1; d < 1024; d <<= 1) {
        int v = 0;
        if (tid >= d) v = sh[tid - d];
        __syncthreads();
        if (tid >= d) sh[tid] += v;
        __syncthreads();
    }
    int run = (tid == 0) ? 0 : sh[tid - 1];
    for (int i = lo; i < hi; i++) {
        g_off[i] = run; g_cur[i] = run; run += g_deg[i];
    }
    if (tid == 1023) g_off[NND] = run;
}
__global__ void k_fill(const int* __restrict__ src, const int* __restrict__ dst, int E) {
    int e = blockIdx.x * blockDim.x + threadIdx.x;
    if (e < E) {
        int p = atomicAdd(&g_cur[dst[e]], 1);
        g_esrc[p] = src[e];
    }
}

// ---------------- GAT attention pieces ----------------
template <int NH, int DD>
__global__ void k_elr(const float* __restrict__ al, const float* __restrict__ ar,
                      int listSel, int cntSel, const int* __restrict__ extList) {
    const int* cntPtr = sel_cnt(cntSel);
    int cnt = cntPtr ? *cntPtr : NND;
    const int* list = sel_list(listSel, extList);
    int totalW = (gridDim.x * blockDim.x) >> 5;
    int gw0 = (blockIdx.x * blockDim.x + threadIdx.x) >> 5;
    int lane = threadIdx.x & 31;
    for (int idx = gw0; idx < cnt; idx += totalW) {
        int gw = list ? list[idx] : idx;
        const float* f = g_F + (size_t)gw * (NH * DD);
#pragma unroll
        for (int h = 0; h < NH; h++) {
            float sl = 0.f, sr = 0.f;
            for (int d = lane; d < DD; d += 32) {
                float v = f[h * DD + d];
                sl += v * al[h * DD + d];
                sr += v * ar[h * DD + d];
            }
#pragma unroll
            for (int o = 16; o; o >>= 1) {
                sl += __shfl_xor_sync(0xffffffffu, sl, o);
                sr += __shfl_xor_sync(0xffffffffu, sr, o);
            }
            if (lane == 0) { g_EL[gw * NH + h] = sl; g_ER[gw * NH + h] = sr; }
        }
    }
}

template <int NH, int DD, bool ACT>
__global__ void k_attn(const float* __restrict__ bias, int outSel,
                       int listSel, int cntSel, const int* __restrict__ extList) {
    constexpr int WID = NH * DD;
    constexpr int NE  = WID / 128;
    constexpr int CE  = 128 / NH;
    float* Hout = (outSel == 1) ? g_HA : g_HB;
    const int* cntPtr = sel_cnt(cntSel);
    int cnt = cntPtr ? *cntPtr : NND;
    const int* list = sel_list(listSel, extList);
    int tid = threadIdx.x;

    __shared__ float s_er[NH], s_m[NH], s_iz[NH];
    __shared__ float red[128];
    __shared__ float swt[32 * NH];
    __shared__ int   ssrc[32];

    for (int bi = blockIdx.x; bi < cnt; bi += gridDim.x) {
        int nd = list ? list[bi] : bi;
        int lo  = g_off[nd];
        int deg = g_off[nd + 1] - lo;

        if (tid < NH) s_er[tid] = g_ER[nd * NH + tid];
        __syncthreads();

        int h  = tid / CE;
        int e0 = tid % CE;
        float erh = s_er[h];

        float lmax = -1e30f;
        for (int e = e0; e < deg; e += CE) {
            int s = g_esrc[lo + e];
            float x = g_EL[s * NH + h] + erh;
            x = x > 0.f ? x : 0.2f * x;
            lmax = fmaxf(lmax, x);
        }
        red[tid] = lmax; __syncthreads();
#pragma unroll
        for (int st = CE / 2; st > 0; st >>= 1) {
            if (e0 < st) red[tid] = fmaxf(red[tid], red[tid + st]);
            __syncthreads();
        }
        if (e0 == 0) s_m[h] = red[tid];
        __syncthreads();
        float mh = s_m[h];

        float lsum = 0.f;
        for (int e = e0; e < deg; e += CE) {
            int s = g_esrc[lo + e];
            float x = g_EL[s * NH + h] + erh;
            x = x > 0.f ? x : 0.2f * x;
            lsum += expf(x - mh);
        }
        red[tid] = lsum; __syncthreads();
#pragma unroll
        for (int st = CE / 2; st > 0; st >>= 1) {
            if (e0 < st) red[tid] += red[tid + st];
            __syncthreads();
        }
        if (e0 == 0) s_iz[h] = 1.f / red[tid];
        __syncthreads();

        float accv[NE];
        int hd[NE];
#pragma unroll
        for (int j = 0; j < NE; j++) { accv[j] = 0.f; hd[j] = (tid + j * 128) / DD; }

        for (int base = 0; base < deg; base += 32) {
            int mcnt = deg - base; if (mcnt > 32) mcnt = 32;
            if (tid < 32 * NH) {
                int eL = tid / NH, hh = tid - (tid / NH) * NH;
                float wv = 0.f;
                if (eL < mcnt) {
                    int s = g_esrc[lo + base + eL];
                    float x = g_EL[s * NH + hh] + s_er[hh];
                    x = x > 0.f ? x : 0.2f * x;
                    wv = expf(x - s_m[hh]) * s_iz[hh];
                    if (hh == 0) ssrc[eL] = s;
                }
                swt[eL * NH + hh] = wv;
            }
            __syncthreads();
            for (int eL = 0; eL < mcnt; eL++) {
                int s = ssrc[eL];
                const float* fr = g_F + (size_t)s * WID;
#pragma unroll
                for (int j = 0; j < NE; j++)
                    accv[j] += swt[eL * NH + hd[j]] * fr[tid + j * 128];
            }
            __syncthreads();
        }

#pragma unroll
        for (int j = 0; j < NE; j++) {
            int c = tid + j * 128;
            float v = accv[j] + bias[c];
            if (ACT) v = v > 0.f ? v : (expf(v) - 1.f);
            Hout[(size_t)nd * WID + c] = v;
        }
    }
}

__global__ void k_out(const int* __restrict__ sid, float* __restrict__ out) {
    int b = blockIdx.x;
    out[(size_t)b * 512 + threadIdx.x] = g_HB[(size_t)sid[b] * 512 + threadIdx.x];
}

// ---------------- launch ----------------
extern "C" void kernel_launch(void* const* d_in, const int* in_sizes, int n_in,
                              void* d_out, int out_size) {
    const int*   all_words      = (const int*)  d_in[0];
    const float* image_feats    = (const float*)d_in[1];
    const int*   sentences      = (const int*)  d_in[2];
    const float* sentence_mask  = (const float*)d_in[3];
    const int*   utterances     = (const int*)  d_in[4];
    const float* utterance_mask = (const float*)d_in[5];
    const int*   session_ids    = (const int*)  d_in[6];
    const int*   edge_src       = (const int*)  d_in[7];
    const int*   edge_dst       = (const int*)  d_in[8];
    const float* word_embed     = (const float*)d_in[9];
    const float* text_fc_w      = (const float*)d_in[10];
    const float* text_fc_b      = (const float*)d_in[11];
    const float* image_fc_w     = (const float*)d_in[12];
    const float* image_fc_b     = (const float*)d_in[13];
    const float* gat0_fc = (const float*)d_in[14];
    const float* gat0_al = (const float*)d_in[15];
    const float* gat0_ar = (const float*)d_in[16];
    const float* gat0_b  = (const float*)d_in[17];
    const float* gat1_fc = (const float*)d_in[18];
    const float* gat1_al = (const float*)d_in[19];
    const float* gat1_ar = (const float*)d_in[20];
    const float* gat1_b  = (const float*)d_in[21];
    const float* gat2_fc = (const float*)d_in[22];
    const float* gat2_al = (const float*)d_in[23];
    const float* gat2_ar = (const float*)d_in[24];
    const float* gat2_b  = (const float*)d_in[25];
    float* out = (float*)d_out;
    int E = in_sizes[7];

    // node features (300-d text space)
    k_word<<<BB * W_, 128>>>(all_words, word_embed);
    k_zero_img<<<BB * I_, 128>>>();
    k_sent<<<BB * S_, 128>>>(sentences, sentence_mask, word_embed);
    k_utt<<<BB * U_, 128>>>(utterances, utterance_mask);
    k_sess<<<BB, 128>>>();

    // text FC: X[8644,300] @ W[300,1024] -> HA
    dim3 gText(1024 / 256, (NND + 127) / 128);
    gemm_big<<<gText, 256>>>(nullptr, 1, text_fc_w, text_fc_b, 1, NND, 1024, 300);

    // image FC via split-K small gemm -> IMF, then scatter into HA
    dim3 gImg(1024 / 128, 4, KS);
    gemm_sk<<<gImg, 256>>>(image_feats, 0, image_fc_w, 256, 1024, 2048, 0, 0, nullptr);
    k_reduce<<<1024, 256>>>(image_fc_b, 4, 1024, 0, 0, 256, nullptr);
    k_scatter_imf<<<BB * I_, 128>>>();

    // active sets: A1 = in-nb(sess), R1 = in-nb(A1)
    k_zero_sets<<<(NND + 255) / 256, 256>>>();
    k_markS<<<1, BB>>>(session_ids);
    k_markA1<<<(E + 255) / 256, 256>>>(edge_src, edge_dst, E);
    k_markR1<<<(E + 255) / 256, 256>>>(edge_src, edge_dst, E);
    k_compact<<<(NND + 255) / 256, 256>>>();

    // CSR by dst
    k_zero_deg<<<(NND + 1 + 255) / 256, 256>>>();
    k_count<<<(E + 255) / 256, 256>>>(edge_dst, E);
    k_scan<<<1, 1024>>>();
    k_fill<<<(E + 255) / 256, 256>>>(edge_src, edge_dst, E);

    // layer 0: HA -> F (full GEMM) -> attn at R1 -> HB
    dim3 gFull(1024 / 256, (NND + 127) / 128);
    gemm_big<<<gFull, 256>>>(nullptr, 2, gat0_fc, nullptr, 3, NND, 1024, 1024);
    k_elr<4, 256><<<512, 128>>>(gat0_al, gat0_ar, 0, 0, nullptr);
    k_attn<4, 256, true><<<2176, 128>>>(gat0_b, 2, 2, 2, nullptr);

    // layer 1: HB rows(R1) -> F (split-K gathered) -> attn at A1 -> HA
    dim3 gL1(1024 / 128, 32, KS);
    gemm_sk<<<gL1, 256>>>(nullptr, 3, gat1_fc, NND, 1024, 1024, 2, 2, nullptr);
    k_reduce<<<1024, 256>>>(nullptr, 3, 1024, 2, 2, NND, nullptr);
    k_elr<4, 256><<<512, 128>>>(gat1_al, gat1_ar, 2, 2, nullptr);
    k_attn<4, 256, true><<<2176, 128>>>(gat1_b, 1, 1, 1, nullptr);

    // layer 2: HA rows(A1) -> F(512) -> attn at session nodes -> HB
    dim3 gL2(512 / 128, 32, KS);
    gemm_sk<<<gL2, 256>>>(nullptr, 2, gat2_fc, NND, 512, 1024, 1, 1, nullptr);
    k_reduce<<<1024, 256>>>(nullptr, 3, 512, 1, 1, NND, nullptr);
    k_elr<1, 512><<<512, 128>>>(gat2_al, gat2_ar, 1, 1, nullptr);
    k_attn<1, 512, false><<<32, 128>>>(gat2_b, 2, 3, 3, session_ids);

    k_out<<<BB, 512>>>(session_ids, out);
}

// round 4
// speedup vs baseline: 3.2381x; 1.3488x over previous
#include <cuda_runtime.h>
#include <cuda_bf16.h>
#include <math.h>
#include <stdint.h>

// Problem constants
#define BB   4
#define W_   2000
#define I_   64
#define S_   64
#define T_   24
#define U_   32
#define US_  2
#define PER_ 2161
#define NND  8644
#define EMAX 147456

// ---------------- scratch (device globals; no allocation) ----------------
__device__ float g_X[NND * 300];
__device__ float g_HA[(size_t)NND * 1024];
__device__ float g_HB[(size_t)NND * 1024];
__device__ float g_F[(size_t)NND * 1024];
__device__ __nv_bfloat16 g_Ah[(size_t)NND * 2048];
__device__ __nv_bfloat16 g_Al[(size_t)NND * 2048];
__device__ __nv_bfloat16 g_Bh[(size_t)1024 * 2048];
__device__ __nv_bfloat16 g_Bl[(size_t)1024 * 2048];
__device__ float g_EL[NND * 4];
__device__ float g_ER[NND * 4];
__device__ int   g_deg[NND + 1];
__device__ int   g_off[NND + 1];
__device__ int   g_cur[NND];
__device__ int   g_esrc[EMAX];
__device__ unsigned char g_S[NND], g_A1f[NND], g_R1f[NND];
__device__ int   g_list1[NND], g_listR[NND], g_listI[256];
__device__ int   g_cnt1, g_cntR;

__device__ __forceinline__ uint32_t smem_u32(const void* p) {
    uint32_t a;
    asm("{ .reg .u64 t; cvta.to.shared.u64 t, %1; cvt.u32.u64 %0, t; }" : "=r"(a) : "l"(p));
    return a;
}

// ---------------- mma.sync helpers ----------------
__device__ __forceinline__ void ldsm_x4(uint32_t* r, uint32_t addr) {
    asm volatile("ldmatrix.sync.aligned.m8n8.x4.shared.b16 {%0,%1,%2,%3}, [%4];"
                 : "=r"(r[0]), "=r"(r[1]), "=r"(r[2]), "=r"(r[3]) : "r"(addr));
}
__device__ __forceinline__ void ldsm_x2(uint32_t* r, uint32_t addr) {
    asm volatile("ldmatrix.sync.aligned.m8n8.x2.shared.b16 {%0,%1}, [%2];"
                 : "=r"(r[0]), "=r"(r[1]) : "r"(addr));
}
__device__ __forceinline__ void mma16816(float* c, const uint32_t* a, const uint32_t* b) {
    asm volatile(
        "mma.sync.aligned.m16n8k16.row.col.f32.bf16.bf16.f32 "
        "{%0,%1,%2,%3},{%4,%5,%6,%7},{%8,%9},{%0,%1,%2,%3};"
        : "+f"(c[0]), "+f"(c[1]), "+f"(c[2]), "+f"(c[3])
        : "r"(a[0]), "r"(a[1]), "r"(a[2]), "r"(a[3]), "r"(b[0]), "r"(b[1]));
}

// ---------------- selectors ----------------
__device__ __forceinline__ const float* sel_in(int s, const float* ext) {
    if (s == 1) return g_X;
    if (s == 2) return g_HA;
    if (s == 3) return g_HB;
    return ext;
}
__device__ __forceinline__ float* sel_out(int s) {
    if (s == 1) return g_HA;
    if (s == 2) return g_HB;
    return g_F;
}
__device__ __forceinline__ const int* sel_list(int s, const int* ext) {
    if (s == 1) return g_list1;
    if (s == 2) return g_listR;
    if (s == 3) return ext;
    if (s == 4) return g_listI;
    return nullptr;
}
__device__ __forceinline__ const int* sel_cnt(int s) {
    if (s == 1) return &g_cnt1;
    if (s == 2) return &g_cntR;
    return nullptr;
}

// ---------------- node feature kernels ----------------
__global__ void k_word(const int* __restrict__ aw, const float* __restrict__ we) {
    int i = blockIdx.x;
    int b = i / W_, w = i - b * W_;
    const float* src = we + (size_t)aw[i] * 300;
    float* dst = g_X + (size_t)(b * PER_ + w) * 300;
    for (int d = threadIdx.x; d < 300; d += blockDim.x) dst[d] = src[d];
}
__global__ void k_zero_img() {
    int r = blockIdx.x;
    int b = r / I_, i = r - b * I_;
    float* dst = g_X + (size_t)(b * PER_ + W_ + i) * 300;
    for (int d = threadIdx.x; d < 300; d += blockDim.x) dst[d] = 0.f;
}
__global__ void k_sent(const int* __restrict__ sent, const float* __restrict__ mask,
                       const float* __restrict__ we) {
    int i = blockIdx.x;
    int b = i / S_, s = i - b * S_;
    const int*   sw = sent + (size_t)i * T_;
    const float* mk = mask + (size_t)i * T_;
    int d0 = threadIdx.x, d1 = d0 + 128, d2 = d0 + 256;
    float cnt = 0.f, a0 = 0.f, a1 = 0.f, a2 = 0.f;
    for (int t = 0; t < T_; t++) {
        float m = mk[t]; cnt += m;
        const float* row = we + (size_t)sw[t] * 300;
        a0 += m * row[d0];
        if (d1 < 300) a1 += m * row[d1];
        if (d2 < 300) a2 += m * row[d2];
    }
    float inv = 1.f / (cnt == 0.f ? 1.f : cnt);
    float* dst = g_X + (size_t)(b * PER_ + W_ + I_ + s) * 300;
    dst[d0] = a0 * inv;
    if (d1 < 300) dst[d1] = a1 * inv;
    if (d2 < 300) dst[d2] = a2 * inv;
}
__global__ void k_utt(const int* __restrict__ utt, const float* __restrict__ mask) {
    int i = blockIdx.x;
    int b = i / U_, u = i - b * U_;
    const int*   ui = utt + (size_t)i * US_;
    const float* mk = mask + (size_t)i * US_;
    int d0 = threadIdx.x, d1 = d0 + 128, d2 = d0 + 256;
    float cnt = 0.f, a0 = 0.f, a1 = 0.f, a2 = 0.f;
    for (int t = 0; t < US_; t++) {
        float m = mk[t]; cnt += m;
        const float* row = g_X + (size_t)(b * PER_ + W_ + I_ + ui[t]) * 300;
        a0 += m * row[d0];
        if (d1 < 300) a1 += m * row[d1];
        if (d2 < 300) a2 += m * row[d2];
    }
    float inv = 1.f / (cnt == 0.f ? 1.f : cnt);
    float* dst = g_X + (size_t)(b * PER_ + W_ + I_ + S_ + u) * 300;
    dst[d0] = a0 * inv;
    if (d1 < 300) dst[d1] = a1 * inv;
    if (d2 < 300) dst[d2] = a2 * inv;
}
__global__ void k_sess() {
    int b = blockIdx.x;
    int d0 = threadIdx.x, d1 = d0 + 128, d2 = d0 + 256;
    float a0 = 0.f, a1 = 0.f, a2 = 0.f;
    for (int u = 0; u < U_; u++) {
        const float* row = g_X + (size_t)(b * PER_ + W_ + I_ + S_ + u) * 300;
        a0 += row[d0];
        if (d1 < 300) a1 += row[d1];
        if (d2 < 300) a2 += row[d2];
    }
    float inv = 1.f / (float)U_;
    float* dst = g_X + (size_t)(b * PER_ + W_ + I_ + S_ + U_) * 300;
    dst[d0] = a0 * inv;
    if (d1 < 300) dst[d1] = a1 * inv;
    if (d2 < 300) dst[d2] = a2 * inv;
}

// ---------------- bf16 hi/lo split kernels ----------------
__device__ __forceinline__ unsigned pack_bf2(__nv_bfloat16 a, __nv_bfloat16 b) {
    __nv_bfloat162 t; t.x = a; t.y = b;
    return *(unsigned*)&t;
}

// A rows (optionally gathered) [cnt, K] fp32 -> g_Ah/g_Al [cnt, KP] bf16 (zero-padded)
__global__ void k_splitA(const float* __restrict__ ext, int srcSel, int K, int KP,
                         int listSel, int cntSel, int cntImm,
                         const int* __restrict__ extList) {
    const int* cp = sel_cnt(cntSel);
    int cnt = cp ? *cp : cntImm;
    const float* A = sel_in(srcSel, ext);
    const int* list = sel_list(listSel, extList);
    int kp4 = KP >> 2;
    long total = (long)cnt * kp4;
    long stride = (long)gridDim.x * blockDim.x;
    for (long i = (long)blockIdx.x * blockDim.x + threadIdx.x; i < total; i += stride) {
        int r = (int)(i / kp4);
        int k = (int)(i - (long)r * kp4) * 4;
        int grow = list ? list[r] : r;
        float4 v = make_float4(0.f, 0.f, 0.f, 0.f);
        if (k < K) v = *(const float4*)(A + (size_t)grow * K + k);
        __nv_bfloat16 h0 = __float2bfloat16(v.x), h1 = __float2bfloat16(v.y);
        __nv_bfloat16 h2 = __float2bfloat16(v.z), h3 = __float2bfloat16(v.w);
        __nv_bfloat16 l0 = __float2bfloat16(v.x - __bfloat162float(h0));
        __nv_bfloat16 l1 = __float2bfloat16(v.y - __bfloat162float(h1));
        __nv_bfloat16 l2 = __float2bfloat16(v.z - __bfloat162float(h2));
        __nv_bfloat16 l3 = __float2bfloat16(v.w - __bfloat162float(h3));
        uint2 H; H.x = pack_bf2(h0, h1); H.y = pack_bf2(h2, h3);
        uint2 L; L.x = pack_bf2(l0, l1); L.y = pack_bf2(l2, l3);
        *(uint2*)(g_Ah + (size_t)r * KP + k) = H;
        *(uint2*)(g_Al + (size_t)r * KP + k) = L;
    }
}

// W [K, N] fp32 -> transposed split g_Bh/g_Bl [N, KP] bf16 (zero-padded)
__global__ void k_splitW(const float* __restrict__ W, int K, int N, int KP) {
    __shared__ float tile[32][33];
    int tx = threadIdx.x, ty = threadIdx.y;
    int nt = blockIdx.x * 32, kt = blockIdx.y * 32;
#pragma unroll
    for (int i = 0; i < 4; i++) {
        int k = kt + ty + i * 8;
        tile[ty + i * 8][tx] = (k < K) ? W[(size_t)k * N + nt + tx] : 0.f;
    }
    __syncthreads();
#pragma unroll
    for (int i = 0; i < 4; i++) {
        int n = nt + ty + i * 8;
        int k = kt + tx;
        float v = tile[tx][ty + i * 8];
        __nv_bfloat16 h = __float2bfloat16(v);
        __nv_bfloat16 l = __float2bfloat16(v - __bfloat162float(h));
        g_Bh[(size_t)n * KP + k] = h;
        g_Bl[(size_t)n * KP + k] = l;
    }
}

__global__ void k_mklistI() {
    int t = threadIdx.x;
    g_listI[t] = (t / I_) * PER_ + W_ + (t % I_);
}

// ---------------- mma.sync bf16x3 GEMM (128x128 block, K-chunk 32) --------
#define SROW 40   // padded bf16 per smem row (80B stride, ldmatrix conflict-free)

__global__ __launch_bounds__(256, 1)
void mma_gemm(int nChunks, int KP, int cSel, int ldC,
              int cntSel, int cntImm, int outListSel,
              const float* __restrict__ bias, const int* __restrict__ extOutList) {
    const int* cp = sel_cnt(cntSel);
    int cnt = cp ? *cp : cntImm;
    int row0 = blockIdx.y * 128;
    if (row0 >= cnt) return;
    int col0 = blockIdx.x * 128;

    __shared__ __align__(16) __nv_bfloat16 sAh[128][SROW];
    __shared__ __align__(16) __nv_bfloat16 sAl[128][SROW];
    __shared__ __align__(16) __nv_bfloat16 sBh[128][SROW];
    __shared__ __align__(16) __nv_bfloat16 sBl[128][SROW];

    int tid = threadIdx.x, lane = tid & 31, wid = tid >> 5;
    int wm = wid & 1, wn = wid >> 1;         // warp tile: 64(M) x 32(N)

    float acc[4][4][4];
#pragma unroll
    for (int i = 0; i < 4; i++)
#pragma unroll
        for (int j = 0; j < 4; j++)
#pragma unroll
            for (int q = 0; q < 4; q++) acc[i][j][q] = 0.f;

    // gmem->smem mapping: each thread moves 2 x uint4 per tile
    int lrow = tid >> 2;                     // 0..63
    int lk   = (tid & 3) * 8;                // 0,8,16,24

    uint32_t bAh = smem_u32(sAh), bAl = smem_u32(sAl);
    uint32_t bBh = smem_u32(sBh), bBl = smem_u32(sBl);

    // ldmatrix lane address components
    int aR = (lane & 15), aC = (lane >> 4) << 3;          // A: x4
    int bR = (lane & 7),  bC = ((lane >> 3) & 1) << 3;    // B: x2 (lanes 0-15)

    for (int c = 0; c < nChunks; c++) {
        int k0g = c * 32;
#pragma unroll
        for (int i = 0; i < 2; i++) {
            int r = lrow + 64 * i;
            int ar = row0 + r;
            bool av = ar < cnt;
            uint4 z = make_uint4(0, 0, 0, 0);
            *(uint4*)&sAh[r][lk] = av ? *(const uint4*)(g_Ah + (size_t)ar * KP + k0g + lk) : z;
            *(uint4*)&sAl[r][lk] = av ? *(const uint4*)(g_Al + (size_t)ar * KP + k0g + lk) : z;
            int br = col0 + r;
            *(uint4*)&sBh[r][lk] = *(const uint4*)(g_Bh + (size_t)br * KP + k0g + lk);
            *(uint4*)&sBl[r][lk] = *(const uint4*)(g_Bl + (size_t)br * KP + k0g + lk);
        }
        __syncthreads();
#pragma unroll
        for (int ks = 0; ks < 2; ks++) {
            int k0 = ks * 16;
            uint32_t ah[4][4], al[4][4], bh[4][2], bl[4][2];
#pragma unroll
            for (int am = 0; am < 4; am++) {
                uint32_t off = (uint32_t)((wm * 64 + am * 16 + aR) * SROW + k0 + aC) * 2;
                ldsm_x4(ah[am], bAh + off);
                ldsm_x4(al[am], bAl + off);
            }
#pragma unroll
            for (int bn = 0; bn < 4; bn++) {
                uint32_t off = (uint32_t)((wn * 32 + bn * 8 + bR) * SROW + k0 + bC) * 2;
                ldsm_x2(bh[bn], bBh + off);
                ldsm_x2(bl[bn], bBl + off);
            }
#pragma unroll
            for (int am = 0; am < 4; am++)
#pragma unroll
                for (int bn = 0; bn < 4; bn++) {
                    mma16816(acc[am][bn], ah[am], bh[bn]);
                    mma16816(acc[am][bn], ah[am], bl[bn]);
                    mma16816(acc[am][bn], al[am], bh[bn]);
                }
        }
        __syncthreads();
    }

    // epilogue: bias + optional row scatter
    const int* ol = sel_list(outListSel, extOutList);
    float* C = sel_out(cSel);
#pragma unroll
    for (int am = 0; am < 4; am++) {
#pragma unroll
        for (int part = 0; part < 2; part++) {
            int r = row0 + wm * 64 + am * 16 + (lane >> 2) + part * 8;
            if (r >= cnt) continue;
            int orow = ol ? ol[r] : r;
            float* dst = C + (size_t)orow * ldC;
#pragma unroll
            for (int bn = 0; bn < 4; bn++) {
                int cidx = col0 + wn * 32 + bn * 8 + (lane & 3) * 2;
                float2 v;
                v.x = acc[am][bn][part * 2 + 0];
                v.y = acc[am][bn][part * 2 + 1];
                if (bias) { v.x += bias[cidx]; v.y += bias[cidx + 1]; }
                *(float2*)&dst[cidx] = v;
            }
        }
    }
}

// ---------------- active-set computation ----------------
__global__ void k_zero_sets() {
    int i = blockIdx.x * blockDim.x + threadIdx.x;
    if (i < NND) { g_S[i] = 0; g_A1f[i] = 0; g_R1f[i] = 0; }
    if (i == 0) { g_cnt1 = 0; g_cntR = 0; }
}
__global__ void k_markS(const int* __restrict__ sid) {
    g_S[sid[threadIdx.x]] = 1;
}
__global__ void k_markA1(const int* __restrict__ src, const int* __restrict__ dst, int E) {
    int e = blockIdx.x * blockDim.x + threadIdx.x;
    if (e < E && g_S[dst[e]]) g_A1f[src[e]] = 1;
}
__global__ void k_markR1(const int* __restrict__ src, const int* __restrict__ dst, int E) {
    int e = blockIdx.x * blockDim.x + threadIdx.x;
    if (e < E && g_A1f[dst[e]]) g_R1f[src[e]] = 1;
}
__global__ void k_compact() {
    int i = blockIdx.x * blockDim.x + threadIdx.x;
    if (i < NND) {
        if (g_A1f[i]) g_list1[atomicAdd(&g_cnt1, 1)] = i;
        if (g_R1f[i]) g_listR[atomicAdd(&g_cntR, 1)] = i;
    }
}

// ---------------- CSR by dst ----------------
__global__ void k_zero_deg() {
    int i = blockIdx.x * blockDim.x + threadIdx.x;
    if (i <= NND) g_deg[i] = 0;
}
__global__ void k_count(const int* __restrict__ dst, int E) {
    int e = blockIdx.x * blockDim.x + threadIdx.x;
    if (e < E) atomicAdd(&g_deg[dst[e]], 1);
}
__global__ void k_scan() {
    __shared__ int sh[1024];
    int tid = threadIdx.x;
    const int chunk = (NND + 1023) >> 10;
    int lo = tid * chunk;
    int hi = lo + chunk; if (hi > NND) hi = NND; if (lo > NND) lo = NND;
    int sum = 0;
    for (int i = lo; i < hi; i++) sum += g_deg[i];
    sh[tid] = sum; __syncthreads();
    for (int d = 1; d < 1024; d <<= 1) {
        int v = 0;
        if (tid >= d) v = sh[tid - d];
        __syncthreads();
        if (tid >= d) sh[tid] += v;
        __syncthreads();
    }
    int run = (tid == 0) ? 0 : sh[tid - 1];
    for (int i = lo; i < hi; i++) {
        g_off[i] = run; g_cur[i] = run; run += g_deg[i];
    }
    if (tid == 1023) g_off[NND] = run;
}
__global__ void k_fill(const int* __restrict__ src, const int* __restrict__ dst, int E) {
    int e = blockIdx.x * blockDim.x + threadIdx.x;
    if (e < E) {
        int p = atomicAdd(&g_cur[dst[e]], 1);
        g_esrc[p] = src[e];
    }
}

// ---------------- GAT attention pieces ----------------
template <int NH, int DD>
__global__ void k_elr(const float* __restrict__ al, const float* __restrict__ ar,
                      int listSel, int cntSel, const int* __restrict__ extList) {
    const int* cp = sel_cnt(cntSel);
    int cnt = cp ? *cp : NND;
    if (cntSel == 0) cnt = NND;
    const int* list = sel_list(listSel, extList);
    int totalW = (gridDim.x * blockDim.x) >> 5;
    int gw0 = (blockIdx.x * blockDim.x + threadIdx.x) >> 5;
    int lane = threadIdx.x & 31;
    for (int idx = gw0; idx < cnt; idx += totalW) {
        int gw = list ? list[idx] : idx;
        const float* f = g_F + (size_t)gw * (NH * DD);
#pragma unroll
        for (int h = 0; h < NH; h++) {
            float sl = 0.f, sr = 0.f;
            for (int d = lane; d < DD; d += 32) {
                float v = f[h * DD + d];
                sl += v * al[h * DD + d];
                sr += v * ar[h * DD + d];
            }
#pragma unroll
            for (int o = 16; o; o >>= 1) {
                sl += __shfl_xor_sync(0xffffffffu, sl, o);
                sr += __shfl_xor_sync(0xffffffffu, sr, o);
            }
            if (lane == 0) { g_EL[gw * NH + h] = sl; g_ER[gw * NH + h] = sr; }
        }
    }
}

template <int NH, int DD, bool ACT>
__global__ void k_attn(const float* __restrict__ bias, int outSel,
                       int listSel, int cntSel, int cntImm,
                       const int* __restrict__ extList) {
    constexpr int WID = NH * DD;
    constexpr int NE  = WID / 128;
    constexpr int CE  = 128 / NH;
    float* Hout = (outSel == 1) ? g_HA : g_HB;
    const int* cp = sel_cnt(cntSel);
    int cnt = cp ? *cp : cntImm;
    const int* list = sel_list(listSel, extList);
    int tid = threadIdx.x;

    __shared__ float s_er[NH], s_m[NH], s_iz[NH];
    __shared__ float red[128];
    __shared__ float swt[32 * NH];
    __shared__ int   ssrc[32];

    for (int bi = blockIdx.x; bi < cnt; bi += gridDim.x) {
        int nd = list ? list[bi] : bi;
        int lo  = g_off[nd];
        int deg = g_off[nd + 1] - lo;

        if (tid < NH) s_er[tid] = g_ER[nd * NH + tid];
        __syncthreads();

        int h  = tid / CE;
        int e0 = tid % CE;
        float erh = s_er[h];

        float lmax = -1e30f;
        for (int e = e0; e < deg; e += CE) {
            int s = g_esrc[lo + e];
            float x = g_EL[s * NH + h] + erh;
            x = x > 0.f ? x : 0.2f * x;
            lmax = fmaxf(lmax, x);
        }
        red[tid] = lmax; __syncthreads();
#pragma unroll
        for (int st = CE / 2; st > 0; st >>= 1) {
            if (e0 < st) red[tid] = fmaxf(red[tid], red[tid + st]);
            __syncthreads();
        }
        if (e0 == 0) s_m[h] = red[tid];
        __syncthreads();
        float mh = s_m[h];

        float lsum = 0.f;
        for (int e = e0; e < deg; e += CE) {
            int s = g_esrc[lo + e];
            float x = g_EL[s * NH + h] + erh;
            x = x > 0.f ? x : 0.2f * x;
            lsum += expf(x - mh);
        }
        red[tid] = lsum; __syncthreads();
#pragma unroll
        for (int st = CE / 2; st > 0; st >>= 1) {
            if (e0 < st) red[tid] += red[tid + st];
            __syncthreads();
        }
        if (e0 == 0) s_iz[h] = 1.f / red[tid];
        __syncthreads();

        float accv[NE];
        int hd[NE];
#pragma unroll
        for (int j = 0; j < NE; j++) { accv[j] = 0.f; hd[j] = (tid + j * 128) / DD; }

        for (int base = 0; base < deg; base += 32) {
            int mcnt = deg - base; if (mcnt > 32) mcnt = 32;
            if (tid < 32 * NH) {
                int eL = tid / NH, hh = tid - (tid / NH) * NH;
                float wv = 0.f;
                if (eL < mcnt) {
                    int s = g_esrc[lo + base + eL];
                    float x = g_EL[s * NH + hh] + s_er[hh];
                    x = x > 0.f ? x : 0.2f * x;
                    wv = expf(x - s_m[hh]) * s_iz[hh];
                    if (hh == 0) ssrc[eL] = s;
                }
                swt[eL * NH + hh] = wv;
            }
            __syncthreads();
            for (int eL = 0; eL < mcnt; eL++) {
                int s = ssrc[eL];
                const float* fr = g_F + (size_t)s * WID;
#pragma unroll
                for (int j = 0; j < NE; j++)
                    accv[j] += swt[eL * NH + hd[j]] * fr[tid + j * 128];
            }
            __syncthreads();
        }

#pragma unroll
        for (int j = 0; j < NE; j++) {
            int c = tid + j * 128;
            float v = accv[j] + bias[c];
            if (ACT) v = v > 0.f ? v : (expf(v) - 1.f);
            Hout[(size_t)nd * WID + c] = v;
        }
    }
}

__global__ void k_out(const int* __restrict__ sid, float* __restrict__ out) {
    int b = blockIdx.x;
    out[(size_t)b * 512 + threadIdx.x] = g_HB[(size_t)sid[b] * 512 + threadIdx.x];
}

// ---------------- launch ----------------
extern "C" void kernel_launch(void* const* d_in, const int* in_sizes, int n_in,
                              void* d_out, int out_size) {
    const int*   all_words      = (const int*)  d_in[0];
    const float* image_feats    = (const float*)d_in[1];
    const int*   sentences      = (const int*)  d_in[2];
    const float* sentence_mask  = (const float*)d_in[3];
    const int*   utterances     = (const int*)  d_in[4];
    const float* utterance_mask = (const float*)d_in[5];
    const int*   session_ids    = (const int*)  d_in[6];
    const int*   edge_src       = (const int*)  d_in[7];
    const int*   edge_dst       = (const int*)  d_in[8];
    const float* word_embed     = (const float*)d_in[9];
    const float* text_fc_w      = (const float*)d_in[10];
    const float* text_fc_b      = (const float*)d_in[11];
    const float* image_fc_w     = (const float*)d_in[12];
    const float* image_fc_b     = (const float*)d_in[13];
    const float* gat0_fc = (const float*)d_in[14];
    const float* gat0_al = (const float*)d_in[15];
    const float* gat0_ar = (const float*)d_in[16];
    const float* gat0_b  = (const float*)d_in[17];
    const float* gat1_fc = (const float*)d_in[18];
    const float* gat1_al = (const float*)d_in[19];
    const float* gat1_ar = (const float*)d_in[20];
    const float* gat1_b  = (const float*)d_in[21];
    const float* gat2_fc = (const float*)d_in[22];
    const float* gat2_al = (const float*)d_in[23];
    const float* gat2_ar = (const float*)d_in[24];
    const float* gat2_b  = (const float*)d_in[25];
    float* out = (float*)d_out;
    int E = in_sizes[7];

    // node features (300-d text space)
    k_word<<<BB * W_, 128>>>(all_words, word_embed);
    k_zero_img<<<BB * I_, 128>>>();
    k_sent<<<BB * S_, 128>>>(sentences, sentence_mask, word_embed);
    k_utt<<<BB * U_, 128>>>(utterances, utterance_mask);
    k_sess<<<BB, 128>>>();
    k_mklistI<<<1, 256>>>();

    // active sets + CSR
    k_zero_sets<<<(NND + 255) / 256, 256>>>();
    k_markS<<<1, BB>>>(session_ids);
    k_markA1<<<(E + 255) / 256, 256>>>(edge_src, edge_dst, E);
    k_markR1<<<(E + 255) / 256, 256>>>(edge_src, edge_dst, E);
    k_compact<<<(NND + 255) / 256, 256>>>();
    k_zero_deg<<<(NND + 1 + 255) / 256, 256>>>();
    k_count<<<(E + 255) / 256, 256>>>(edge_dst, E);
    k_scan<<<1, 1024>>>();
    k_fill<<<(E + 255) / 256, 256>>>(edge_src, edge_dst, E);

    dim3 tb(32, 8);

    // text FC: g_X [NND,300] @ W[300,1024] + b -> g_HA   (KP=320)
    k_splitW<<<dim3(1024 / 32, 320 / 32), tb>>>(text_fc_w, 300, 1024, 320);
    k_splitA<<<1024, 256>>>(nullptr, 1, 300, 320, 0, 0, NND, nullptr);
    mma_gemm<<<dim3(8, 68), 256>>>(10, 320, 1, 1024, 0, NND, 0, text_fc_b, nullptr);

    // image FC: image_feats [256,2048] @ W[2048,1024] + b -> g_HA rows(listI)
    k_splitW<<<dim3(1024 / 32, 2048 / 32), tb>>>(image_fc_w, 2048, 1024, 2048);
    k_splitA<<<1024, 256>>>(image_feats, 0, 2048, 2048, 0, 0, 256, nullptr);
    mma_gemm<<<dim3(8, 2), 256>>>(64, 2048, 1, 1024, 0, 256, 4, image_fc_b, nullptr);

    // layer 0: g_HA [NND,1024] @ gat0_fc -> g_F ; attn over R1 -> g_HB
    k_splitW<<<dim3(1024 / 32, 1024 / 32), tb>>>(gat0_fc, 1024, 1024, 1024);
    k_splitA<<<1024, 256>>>(nullptr, 2, 1024, 1024, 0, 0, NND, nullptr);
    mma_gemm<<<dim3(8, 68), 256>>>(32, 1024, 3, 1024, 0, NND, 0, nullptr, nullptr);
    k_elr<4, 256><<<512, 128>>>(gat0_al, gat0_ar, 0, 0, nullptr);
    k_attn<4, 256, true><<<2176, 128>>>(gat0_b, 2, 2, 2, NND, nullptr);

    // layer 1: g_HB rows(listR) @ gat1_fc -> g_F(listR) ; attn over A1 -> g_HA
    k_splitW<<<dim3(1024 / 32, 1024 / 32), tb>>>(gat1_fc, 1024, 1024, 1024);
    k_splitA<<<1024, 256>>>(nullptr, 3, 1024, 1024, 2, 2, 0, nullptr);
    mma_gemm<<<dim3(8, 68), 256>>>(32, 1024, 3, 1024, 2, 0, 2, nullptr, nullptr);
    k_elr<4, 256><<<512, 128>>>(gat1_al, gat1_ar, 2, 2, nullptr);
    k_attn<4, 256, true><<<2176, 128>>>(gat1_b, 1, 1, 1, 0, nullptr);

    // layer 2: g_HA rows(list1) @ gat2_fc[1024,512] -> g_F(list1, ld=512);
    // attn over 4 session nodes -> g_HB
    k_splitW<<<dim3(512 / 32, 1024 / 32), tb>>>(gat2_fc, 1024, 512, 1024);
    k_splitA<<<1024, 256>>>(nullptr, 2, 1024, 1024, 1, 1, 0, nullptr);
    mma_gemm<<<dim3(4, 2), 256>>>(32, 1024, 3, 512, 1, 0, 1, nullptr, nullptr);
    k_elr<1, 512><<<512, 128>>>(gat2_al, gat2_ar, 1, 1, nullptr);
    k_attn<1, 512, false><<<32, 128>>>(gat2_b, 2, 3, 0, BB, session_ids);

    k_out<<<BB, 512>>>(session_ids, out);
}